// round 9
// baseline (speedup 1.0000x reference)
#include <cuda_runtime.h>
#include <math.h>

#define NN   32
#define CIN  32
#define CO   16
#define DD   16
#define SSP  256
#define MM   8192

// ---- scratch ----
__device__ float d_b [NN*MM*CO];       // 16 MB: b[n][c*256+s][o]  (o-contiguous)
__device__ float d_E [NN*MM*CO];       // 16 MB: exp(b - blockmax), same layout
__device__ float d_S [3*NN*CO*DD];     // triple-buffered routed sums
__device__ float d_pm[NN*CO*CIN];      // per-block softmax max     [n][o][c]
__device__ float d_ps[NN*CO*CIN];      // per-block softmax expsum  [n][o][c]

// fast exp via FMA pipe: 2^(x*log2e), range-reduced, Taylor-6 (rel err ~1e-7)
__device__ __forceinline__ float fexp(float x) {
    x = fmaxf(x, -87.0f);
    float z = x * 1.4426950408889634f;
    float kf = z + 12582912.0f;              // round-to-nearest magic (1.5*2^23)
    int   ki = __float_as_int(kf);
    float n  = kf - 12582912.0f;
    float f  = z - n;
    float p  = 1.5252733804e-4f;
    p = fmaf(p, f, 1.3333558146e-3f);
    p = fmaf(p, f, 9.6181291076e-3f);
    p = fmaf(p, f, 5.5504108664e-2f);
    p = fmaf(p, f, 2.4022650696e-1f);
    p = fmaf(p, f, 6.9314718056e-1f);
    p = fmaf(p, f, 1.0f);
    float s = __int_as_float((ki + 127) << 23);
    return p * s;
}

// Gp[o, i*4+j] = sum_k W[c,o,j,k] * g[o, i*4+k]   (one entry per thread)
__device__ __forceinline__ void gp_compute(const float* wsh, const float* gsh,
                                           float* gpsh, int t) {
    int o = t >> 4, i = (t >> 2) & 3, j = t & 3;
    float a = 0.f;
#pragma unroll
    for (int k = 0; k < 4; k++)
        a += wsh[o*16 + j*4 + k] * gsh[o*16 + i*4 + k];
    gpsh[t] = a;
}

// bb[o] += sum_d Gp[o,d]*lv[d]  (float4 broadcast LDS)
__device__ __forceinline__ void b_accum(float bb[16], const float4* gp4, const float lv[16]) {
#pragma unroll
    for (int o = 0; o < 16; o++) {
        float4 a0 = gp4[o*4+0], a1 = gp4[o*4+1], a2 = gp4[o*4+2], a3 = gp4[o*4+3];
        bb[o] += a0.x*lv[0] + a0.y*lv[1] + a0.z*lv[2] + a0.w*lv[3]
               + a1.x*lv[4] + a1.y*lv[5] + a1.z*lv[6] + a1.w*lv[7]
               + a2.x*lv[8] + a2.y*lv[9] + a2.z*lv[10]+ a2.w*lv[11]
               + a3.x*lv[12]+ a3.y*lv[13]+ a3.z*lv[14]+ a3.w*lv[15];
    }
}

// shared tail for binit/badd: write b, compute blockmax, E, partial sums.
// bsh: float[16*272] transpose scratch; mxsh: float[16].
#define BSTR 272
__device__ __forceinline__ void b_tail(float bb[16], int bid, int n, int c, int t,
                                       float* bsh, float* mxsh) {
    // store b (o-contiguous, 4x STG.128)
    {
        float4* bp = (float4*)d_b + ((size_t)bid*256 + t)*4;
#pragma unroll
        for (int q = 0; q < 4; q++)
            bp[q] = make_float4(bb[q*4], bb[q*4+1], bb[q*4+2], bb[q*4+3]);
    }
    // transpose bb -> bsh[o][s]
#pragma unroll
    for (int o = 0; o < 16; o++) bsh[o*BSTR + t] = bb[o];
    __syncthreads();
    int o = t >> 4, seg = t & 15;
    // block max per o
    {
        float m = -3.4e38f;
#pragma unroll
        for (int j = 0; j < 16; j++) m = fmaxf(m, bsh[o*BSTR + seg + 16*j]);
#pragma unroll
        for (int off = 1; off < 16; off <<= 1)
            m = fmaxf(m, __shfl_xor_sync(0xffffffffu, m, off));
        if (seg == 0) mxsh[o] = m;
    }
    __syncthreads();
    // E = fexp(b - blockmax); store E to global and bsh
    {
        float ee[16];
#pragma unroll
        for (int oo = 0; oo < 16; oo++) ee[oo] = fexp(bb[oo] - mxsh[oo]);
        float4* ep = (float4*)d_E + ((size_t)bid*256 + t)*4;
#pragma unroll
        for (int q = 0; q < 4; q++)
            ep[q] = make_float4(ee[q*4], ee[q*4+1], ee[q*4+2], ee[q*4+3]);
#pragma unroll
        for (int oo = 0; oo < 16; oo++) bsh[oo*BSTR + t] = ee[oo];
    }
    __syncthreads();
    // partial expsum per o
    {
        float s = 0.f;
#pragma unroll
        for (int j = 0; j < 16; j++) s += bsh[o*BSTR + seg + 16*j];
#pragma unroll
        for (int off = 1; off < 16; off <<= 1)
            s += __shfl_xor_sync(0xffffffffu, s, off);
        if (seg == 0) {
            d_pm[(n*16 + o)*32 + c] = mxsh[o];
            d_ps[(n*16 + o)*32 + c] = s;
        }
    }
}

// ---------- binit: Gp(g0), b = lp.Gp, E + partials; zero S ----------
__global__ void __launch_bounds__(256) binit_kernel(const float* __restrict__ l,
                                                    const float* __restrict__ g,
                                                    const float* __restrict__ w) {
    __shared__ float wsh[256], gsh[256];
    __shared__ __align__(16) float gpsh[256];
    __shared__ float bsh[16*BSTR];
    __shared__ float mxsh[16];
    int bid = blockIdx.x; int n = bid >> 5, c = bid & 31; int t = threadIdx.x;
    wsh[t] = w[c*256 + t];
    gsh[t] = g[n*256 + t];
    if (bid < 96) d_S[bid*256 + t] = 0.f;
    __syncthreads();
    gp_compute(wsh, gsh, gpsh, t);
    __syncthreads();
    float lv[16];
    const float* lb = l + (size_t)bid*4096 + t;
#pragma unroll
    for (int d = 0; d < 16; d++) lv[d] = lb[d*256];
    float bb[16];
#pragma unroll
    for (int o = 0; o < 16; o++) bb[o] = 0.f;
    b_accum(bb, (const float4*)gpsh, lv);
    b_tail(bb, bid, n, c, t, bsh, mxsh);
}

// ---------- badd: squash(S), Gp, b += lp.Gp, E + partials ----------
__global__ void __launch_bounds__(256) badd_kernel(const float* __restrict__ l,
                                                   const float* __restrict__ w, int sbuf) {
    __shared__ float wsh[256], gsh[256];
    __shared__ __align__(16) float gpsh[256];
    __shared__ float bsh[16*BSTR];
    __shared__ float mxsh[16];
    int bid = blockIdx.x; int n = bid >> 5, c = bid & 31; int t = threadIdx.x;
    wsh[t] = w[c*256 + t];
    {
        float sv = d_S[sbuf*8192 + n*256 + t];
        float n2 = sv*sv;
#pragma unroll
        for (int off = 1; off < 16; off <<= 1)
            n2 += __shfl_xor_sync(0xffffffffu, n2, off);
        float nn = sqrtf(n2);
        gsh[t] = sv * (n2 / ((1.f + n2) * (nn + 1e-6f)));
    }
    __syncthreads();
    gp_compute(wsh, gsh, gpsh, t);
    __syncthreads();
    float lv[16];
    const float* lb = l + (size_t)bid*4096 + t;
#pragma unroll
    for (int d = 0; d < 16; d++) lv[d] = lb[d*256];
    float bb[16];
    {
        const float4* bp = (const float4*)d_b + ((size_t)bid*256 + t)*4;
#pragma unroll
        for (int q = 0; q < 4; q++) {
            float4 v = bp[q];
            bb[q*4] = v.x; bb[q*4+1] = v.y; bb[q*4+2] = v.z; bb[q*4+3] = v.w;
        }
    }
    b_accum(bb, (const float4*)gpsh, lv);
    b_tail(bb, bid, n, c, t, bsh, mxsh);
}

// ---------- t: stats merge (max-first), cc = E*scale, matmul, W-mult, S atomics ----------
#define LSTR 260
template <bool LAST>
__global__ void __launch_bounds__(256) t_kernel(const float* __restrict__ l,
                                                const float* __restrict__ w,
                                                float* __restrict__ out_a, int sbuf) {
    __shared__ __align__(16) float lsh[16*LSTR];   // l[d][s]
    __shared__ __align__(16) float csh[16*LSTR];   // cc[o][s]
    __shared__ float wsh[256];
    __shared__ float sclsh[16];
    __shared__ float tsh[16*17];
    int bid = blockIdx.x; int n = bid >> 5, c = bid & 31; int t = threadIdx.x;
    wsh[t] = w[c*256 + t];
    // merge softmax partials: global max (no exp), then scaled-sum merge (2 fexp)
    {
        int o = t >> 4, l16 = t & 15;
        int base = (n*16 + o)*32;
        float m1 = d_pm[base + l16],      s1 = d_ps[base + l16];
        float m2 = d_pm[base + 16 + l16], s2 = d_ps[base + 16 + l16];
        float M = fmaxf(m1, m2);
#pragma unroll
        for (int off = 1; off < 16; off <<= 1)
            M = fmaxf(M, __shfl_xor_sync(0xffffffffu, M, off));
        float S = s1*fexp(m1 - M) + s2*fexp(m2 - M);
#pragma unroll
        for (int off = 1; off < 16; off <<= 1)
            S += __shfl_xor_sync(0xffffffffu, S, off);
        if (l16 == (c & 15)) {
            float pm_self = (c < 16) ? m1 : m2;
            sclsh[o] = fexp(pm_self - M) / S;   // cc = E * scale
        }
    }
    // stage l: 4x LDG.128 -> STS.128 into d-major lsh (no transpose needed)
    {
        const float4* lg = (const float4*)(l + (size_t)bid*4096);
        float4* lsh4 = (float4*)lsh;
#pragma unroll
        for (int j = 0; j < 4; j++) {
            int u = t + 256*j;
            lsh4[(u >> 6)*65 + (u & 63)] = lg[u];
        }
    }
    // load E for s = t
    float4 e4[4];
    {
        const float4* ep = (const float4*)d_E + ((size_t)bid*256 + t)*4;
#pragma unroll
        for (int q = 0; q < 4; q++) e4[q] = ep[q];
    }
    __syncthreads();
    // cc[o] = E[o]*scale[o]; stage o-major; last iter writes a
    {
        float cc[16];
#pragma unroll
        for (int q = 0; q < 4; q++) {
            cc[q*4+0] = e4[q].x * sclsh[q*4+0];
            cc[q*4+1] = e4[q].y * sclsh[q*4+1];
            cc[q*4+2] = e4[q].z * sclsh[q*4+2];
            cc[q*4+3] = e4[q].w * sclsh[q*4+3];
        }
#pragma unroll
        for (int o = 0; o < 16; o++) csh[o*LSTR + t] = cc[o];
        if (LAST) {
            float4* dst = (float4*)(out_a + ((size_t)bid*256 + t)*16);
#pragma unroll
            for (int q = 0; q < 4; q++)
                dst[q] = make_float4(cc[q*4], cc[q*4+1], cc[q*4+2], cc[q*4+3]);
        }
    }
    __syncthreads();
    // matmul: thread (o,d) computes T[o,d] = sum_s cc[o][s]*l[d][s]
    {
        int o = t >> 4, d = t & 15;
        const float4* csh4 = (const float4*)csh + o*65;
        const float4* lsh4 = (const float4*)lsh + d*65;
        float ax = 0.f, ay = 0.f, az = 0.f, aw = 0.f;
#pragma unroll
        for (int s4 = 0; s4 < 64; s4++) {
            float4 cv = csh4[s4];
            float4 lv2 = lsh4[s4];
            ax = fmaf(cv.x, lv2.x, ax);
            ay = fmaf(cv.y, lv2.y, ay);
            az = fmaf(cv.z, lv2.z, az);
            aw = fmaf(cv.w, lv2.w, aw);
        }
        tsh[o*17 + d] = (ax + ay) + (az + aw);
    }
    __syncthreads();
    // V[o,i,kk] = sum_j T[o,i*4+j]*W[c,o,j,kk]; atomic into S (addr == t)
    {
        int o = t >> 4, i = (t >> 2) & 3, kk = t & 3;
        float v = 0.f;
#pragma unroll
        for (int j = 0; j < 4; j++)
            v += tsh[o*17 + i*4 + j] * wsh[o*16 + j*4 + kk];
        atomicAdd(&d_S[sbuf*8192 + n*256 + t], v);
    }
}

// ---------- final g output ----------
__global__ void __launch_bounds__(256) squash_out_kernel(float* __restrict__ out_g, int sbuf) {
    int n = blockIdx.x; int t = threadIdx.x;
    float sv = d_S[sbuf*8192 + n*256 + t];
    float n2 = sv*sv;
#pragma unroll
    for (int off = 1; off < 16; off <<= 1)
        n2 += __shfl_xor_sync(0xffffffffu, n2, off);
    float nn = sqrtf(n2);
    out_g[n*256 + t] = sv * (n2 / ((1.f + n2) * (nn + 1e-6f)));
}

extern "C" void kernel_launch(void* const* d_in, const int* in_sizes, int n_in,
                              void* d_out, int out_size) {
    const float* l = (const float*)d_in[0];   // (32,32,16,16,16)
    const float* g = (const float*)d_in[1];   // (32,16,16)
    const float* w = (const float*)d_in[2];   // (1,32,1,16,4,4)
    float* out_a = (float*)d_out;             // (32, 8192, 16)
    float* out_g = out_a + (size_t)NN*MM*CO;  // (32, 16, 16)

    binit_kernel<<<NN*CIN, 256>>>(l, g, w);
    t_kernel<false><<<NN*CIN, 256>>>(l, w, nullptr, 0);   // iter 0
    badd_kernel<<<NN*CIN, 256>>>(l, w, 0);
    t_kernel<false><<<NN*CIN, 256>>>(l, w, nullptr, 1);   // iter 1
    badd_kernel<<<NN*CIN, 256>>>(l, w, 1);
    t_kernel<true><<<NN*CIN, 256>>>(l, w, out_a, 2);      // iter 2 (+a)
    squash_out_kernel<<<NN, 256>>>(out_g, 2);
}